// round 6
// baseline (speedup 1.0000x reference)
#include <cuda_runtime.h>
#include <cuda_bf16.h>
#include <math.h>
#include <stdint.h>

#define Bn    2
#define Sn    2048
#define DIN   2048
#define Hn    16
#define Gn    4
#define HD    128
#define DOUT  2048
#define GROUPn 4          // H / G
#define EPSf  1e-6f
#define Mrows (Bn*Sn)     // 4096

// ---------------- scratch (device globals; no allocation allowed) ----------
__device__ float g_QG  [(size_t)Bn*Sn*Hn*2*HD];   // [b,s,h,2*HD]  (q | gate)
__device__ float g_KV  [(size_t)Bn*Sn*(2*Gn*HD)]; // [b,s, K(512) | V(512)]

// bf16 hi/lo attention operands
__device__ __nv_bfloat16 g_Qh[(size_t)Bn*Hn*Sn*HD];
__device__ __nv_bfloat16 g_Ql[(size_t)Bn*Hn*Sn*HD];
__device__ __nv_bfloat16 g_Kh[(size_t)Bn*Gn*Sn*HD];
__device__ __nv_bfloat16 g_Kl[(size_t)Bn*Gn*Sn*HD];
__device__ __nv_bfloat16 g_Vh[(size_t)Bn*Gn*Sn*HD];
__device__ __nv_bfloat16 g_Vl[(size_t)Bn*Gn*Sn*HD];

// bf16 split scratch for GEMMs
__device__ __nv_bfloat16 g_xh  [(size_t)Mrows*DIN];
__device__ __nv_bfloat16 g_xl  [(size_t)Mrows*DIN];
__device__ __nv_bfloat16 g_Wqh [(size_t)(2*DOUT)*DIN];
__device__ __nv_bfloat16 g_Wql [(size_t)(2*DOUT)*DIN];
__device__ __nv_bfloat16 g_Wkvh[(size_t)(2*Gn*HD)*DIN];  // [K(512)|V(512)][2048]
__device__ __nv_bfloat16 g_Wkvl[(size_t)(2*Gn*HD)*DIN];
__device__ __nv_bfloat16 g_Woh [(size_t)DIN*DOUT];
__device__ __nv_bfloat16 g_Wol [(size_t)DIN*DOUT];
__device__ __nv_bfloat16 g_Cxh [(size_t)Mrows*DOUT];
__device__ __nv_bfloat16 g_Cxl [(size_t)Mrows*DOUT];

// ======================= PTX helpers (compute_103 baseline only) ==========
__device__ __forceinline__ uint32_t smem_u32(const void* p) {
    uint32_t a;
    asm("{ .reg .u64 t; cvta.to.shared.u64 t, %1; cvt.u32.u64 %0, t; }" : "=r"(a) : "l"(p));
    return a;
}
// single-instruction bulk copy global -> shared, completion on mbarrier
__device__ __forceinline__ void cpbulk(uint32_t s, const void* g, uint32_t bytes, uint32_t mbar) {
    asm volatile(
        "cp.async.bulk.shared::cta.global.mbarrier::complete_tx::bytes [%0], [%1], %2, [%3];"
        :: "r"(s), "l"(g), "r"(bytes), "r"(mbar) : "memory");
}
#define MBAR_INIT(m, c) \
    asm volatile("mbarrier.init.shared.b64 [%0], %1;" :: "r"(m), "r"(c) : "memory")
#define MBAR_EXPECT(m, b) \
    asm volatile("mbarrier.arrive.expect_tx.shared.b64 _, [%0], %1;" :: "r"(m), "r"(b) : "memory")
#define MBAR_WAIT(mbar, parity) do { \
    uint32_t _m = (mbar); uint32_t _p = (parity); uint32_t _d; \
    asm volatile("{\n\t.reg .pred p;\n\t" \
        "mbarrier.try_wait.parity.acquire.cta.shared::cta.b64 p, [%1], %2;\n\t" \
        "selp.b32 %0, 1, 0, p;\n\t}" : "=r"(_d) : "r"(_m), "r"(_p) : "memory"); \
    if (!_d) { \
        asm volatile("{\n\t.reg .pred P1;\n\t" \
            "WL_%=:\n\t" \
            "mbarrier.try_wait.parity.acquire.cta.shared::cta.b64 P1, [%0], %1, 0x989680;\n\t" \
            "@P1 bra.uni WD_%=;\n\t" \
            "bra.uni WL_%=;\n\t" \
            "WD_%=:\n\t}" :: "r"(_m), "r"(_p) : "memory"); \
    } } while (0)

__device__ __forceinline__ void ldsm_x4(uint32_t* r, uint32_t addr) {
    asm volatile("ldmatrix.sync.aligned.m8n8.x4.shared.b16 {%0,%1,%2,%3}, [%4];"
        : "=r"(r[0]), "=r"(r[1]), "=r"(r[2]), "=r"(r[3]) : "r"(addr));
}
__device__ __forceinline__ void ldsm_x4t(uint32_t* r, uint32_t addr) {
    asm volatile("ldmatrix.sync.aligned.m8n8.x4.trans.shared.b16 {%0,%1,%2,%3}, [%4];"
        : "=r"(r[0]), "=r"(r[1]), "=r"(r[2]), "=r"(r[3]) : "r"(addr));
}
__device__ __forceinline__ void mma16816(float* d, const uint32_t* a, const uint32_t* b) {
    asm volatile(
        "mma.sync.aligned.m16n8k16.row.col.f32.bf16.bf16.f32 "
        "{%0,%1,%2,%3}, {%4,%5,%6,%7}, {%8,%9}, {%0,%1,%2,%3};"
        : "+f"(d[0]), "+f"(d[1]), "+f"(d[2]), "+f"(d[3])
        : "r"(a[0]), "r"(a[1]), "r"(a[2]), "r"(a[3]), "r"(b[0]), "r"(b[1]));
}
__device__ __forceinline__ float ex2f(float x) {
    float r; asm("ex2.approx.f32 %0, %1;" : "=f"(r) : "f"(x)); return r;
}
__device__ __forceinline__ uint32_t packbf2(float lo, float hi) {
    uint32_t r; asm("cvt.rn.bf16x2.f32 %0, %1, %2;" : "=r"(r) : "f"(hi), "f"(lo)); return r;
}

// ======================= split / transpose-split ==========================
__global__ __launch_bounds__(256) void fsplit(const float* __restrict__ in,
                                              __nv_bfloat16* __restrict__ h,
                                              __nv_bfloat16* __restrict__ l, int n)
{
    int i = (blockIdx.x * 256 + threadIdx.x) * 4;
    if (i >= n) return;
    float4 v = *(const float4*)(in + i);
    __nv_bfloat16 h0 = __float2bfloat16(v.x), h1 = __float2bfloat16(v.y);
    __nv_bfloat16 h2 = __float2bfloat16(v.z), h3 = __float2bfloat16(v.w);
    __nv_bfloat16 l0 = __float2bfloat16(v.x - __bfloat162float(h0));
    __nv_bfloat16 l1 = __float2bfloat16(v.y - __bfloat162float(h1));
    __nv_bfloat16 l2 = __float2bfloat16(v.z - __bfloat162float(h2));
    __nv_bfloat16 l3 = __float2bfloat16(v.w - __bfloat162float(h3));
    *(__nv_bfloat162*)(h + i)     = __nv_bfloat162(h0, h1);
    *(__nv_bfloat162*)(h + i + 2) = __nv_bfloat162(h2, h3);
    *(__nv_bfloat162*)(l + i)     = __nv_bfloat162(l0, l1);
    *(__nv_bfloat162*)(l + i + 2) = __nv_bfloat162(l2, l3);
}

// W[K,N] fp32 -> Th/Tl[N,K] bf16 (transpose + split)
__global__ __launch_bounds__(256) void tsplit(const float* __restrict__ W,
                                              __nv_bfloat16* __restrict__ Th,
                                              __nv_bfloat16* __restrict__ Tl,
                                              int K, int N)
{
    __shared__ float t[32][33];
    const int n0 = blockIdx.x * 32, k0 = blockIdx.y * 32;
    const int tx = threadIdx.x, ty = threadIdx.y;  // (32, 8)
    #pragma unroll
    for (int r = 0; r < 4; r++)
        t[ty + r * 8][tx] = W[(size_t)(k0 + ty + r * 8) * N + n0 + tx];
    __syncthreads();
    #pragma unroll
    for (int r = 0; r < 4; r++) {
        int n = n0 + ty + r * 8, k = k0 + tx;
        float v = t[tx][ty + r * 8];
        __nv_bfloat16 h = __float2bfloat16(v);
        __nv_bfloat16 l = __float2bfloat16(v - __bfloat162float(h));
        Th[(size_t)n * K + k] = h;
        Tl[(size_t)n * K + k] = l;
    }
}

// ======================= HMMA split-bf16 GEMM (256x128 tile, bulk-copy) ====
// C[M,N] = A[M,K] * B^T, A (hi/lo) [M,K], Bt (hi/lo) [N,K], K-major bf16.
// 256 threads (8 warps as 4m x 2n), warp tile 64x64, K-chunk 32.
#define GBK    32
#define LDS    40
#define ATILEB (256 * LDS * 2)   // 20480 B
#define BTILEB (128 * LDS * 2)   // 10240 B
#define STAGEB (2 * ATILEB + 2 * BTILEB)  // 61440 B
#define GEMM_SMEM (2 * STAGEB)            // 122880 B
#define OFF_AL  ATILEB
#define OFF_BH  (2 * ATILEB)
#define OFF_BL  (2 * ATILEB + BTILEB)
#define STG_BYTES ((256 + 256 + 128 + 128) * 64)   // 49152

__device__ __forceinline__ void load_stage_bulk(
    uint32_t smb, int stage, uint32_t mbar,
    const __nv_bfloat16* __restrict__ pAh, const __nv_bfloat16* __restrict__ pAl,
    const __nv_bfloat16* __restrict__ pBh, const __nv_bfloat16* __restrict__ pBl,
    int K, int kc, int tid)
{
    const uint32_t sb = smb + stage * STAGEB;
    // A: 256 rows hi + 256 rows lo, one 64B row per bulk
    cpbulk(sb + (uint32_t)tid * 80,          pAh + (size_t)tid * K + kc, 64, mbar);
    cpbulk(sb + OFF_AL + (uint32_t)tid * 80, pAl + (size_t)tid * K + kc, 64, mbar);
    // B: 128 rows hi (threads 0-127) + 128 rows lo (threads 128-255)
    if (tid < 128) {
        cpbulk(sb + OFF_BH + (uint32_t)tid * 80, pBh + (size_t)tid * K + kc, 64, mbar);
    } else {
        const int row = tid - 128;
        cpbulk(sb + OFF_BL + (uint32_t)row * 80, pBl + (size_t)row * K + kc, 64, mbar);
    }
}

__global__ __launch_bounds__(256, 1) void gemm_tc(
    const __nv_bfloat16* __restrict__ Ah, const __nv_bfloat16* __restrict__ Al,
    const __nv_bfloat16* __restrict__ Bh, const __nv_bfloat16* __restrict__ Bl,
    float* __restrict__ C, int M, int N, int K)
{
    extern __shared__ char sm[];
    __shared__ uint64_t mb[2];
    const uint32_t smb = smem_u32(sm);
    const uint32_t m0 = smem_u32(&mb[0]), m1 = smem_u32(&mb[1]);
    const int tid  = threadIdx.x;
    const int wid  = tid >> 5, lane = tid & 31;
    const int wm   = wid & 3;           // 4 m-warps x 64 rows
    const int wn   = wid >> 2;          // 2 n-warps x 64 cols
    const int mbr  = blockIdx.y * 256, nbr = blockIdx.x * 128;

    const __nv_bfloat16* pAh = Ah + (size_t)mbr * K;
    const __nv_bfloat16* pAl = Al + (size_t)mbr * K;
    const __nv_bfloat16* pBh = Bh + (size_t)nbr * K;
    const __nv_bfloat16* pBl = Bl + (size_t)nbr * K;

    float acc[4][8][4];
    #pragma unroll
    for (int i = 0; i < 4; i++)
        #pragma unroll
        for (int j = 0; j < 8; j++)
            #pragma unroll
            for (int k = 0; k < 4; k++) acc[i][j][k] = 0.f;

    const uint32_t aoff = (uint32_t)((wm * 64 + (lane & 15)) * LDS + ((lane >> 4) * 8)) * 2;
    const uint32_t boff = (uint32_t)((wn * 64 + (lane & 7) + ((lane >> 4) << 3)) * LDS
                                     + (((lane >> 3) & 1) * 8)) * 2;

    if (tid == 0) { MBAR_INIT(m0, 1); MBAR_INIT(m1, 1); }
    __syncthreads();

    const int NC = K / GBK;
    if (tid == 0) MBAR_EXPECT(m0, STG_BYTES);
    load_stage_bulk(smb, 0, m0, pAh, pAl, pBh, pBl, K, 0, tid);
    int ph0 = 0, ph1 = 0;

    for (int c = 0; c < NC; c++) {
        if (c + 1 < NC) {
            const uint32_t mn = ((c + 1) & 1) ? m1 : m0;
            if (tid == 0) MBAR_EXPECT(mn, STG_BYTES);
            load_stage_bulk(smb, (c + 1) & 1, mn, pAh, pAl, pBh, pBl, K, (c + 1) * GBK, tid);
        }
        if ((c & 1) == 0) { MBAR_WAIT(m0, ph0); ph0 ^= 1; }
        else             { MBAR_WAIT(m1, ph1); ph1 ^= 1; }

        const uint32_t st = smb + (c & 1) * STAGEB;
        #pragma unroll
        for (int ks = 0; ks < 2; ks++) {
            const uint32_t kb = ks * 32;
            uint32_t bh[16], bl[16];
            #pragma unroll
            for (int n16 = 0; n16 < 4; n16++) {
                ldsm_x4(bh + 4 * n16, st + OFF_BH + boff + n16 * (16 * LDS * 2) + kb);
                ldsm_x4(bl + 4 * n16, st + OFF_BL + boff + n16 * (16 * LDS * 2) + kb);
            }
            #pragma unroll
            for (int mf = 0; mf < 4; mf++) {
                uint32_t ah[4], al[4];
                ldsm_x4(ah, st + aoff + mf * (16 * LDS * 2) + kb);
                ldsm_x4(al, st + OFF_AL + aoff + mf * (16 * LDS * 2) + kb);
                #pragma unroll
                for (int nf = 0; nf < 8; nf++) {
                    const uint32_t* bhp = &bh[(nf >> 1) * 4 + (nf & 1) * 2];
                    const uint32_t* blp = &bl[(nf >> 1) * 4 + (nf & 1) * 2];
                    mma16816(acc[mf][nf], ah, bhp);
                    mma16816(acc[mf][nf], ah, blp);
                    mma16816(acc[mf][nf], al, bhp);
                }
            }
        }
        __syncthreads();   // release buffer c&1 for reissue at c+2
    }

    #pragma unroll
    for (int mf = 0; mf < 4; mf++) {
        const int r0 = mbr + wm * 64 + mf * 16 + (lane >> 2);
        #pragma unroll
        for (int nf = 0; nf < 8; nf++) {
            const int n0 = nbr + wn * 64 + nf * 8 + (lane & 3) * 2;
            *(float2*)(C + (size_t)r0 * N + n0)       = make_float2(acc[mf][nf][0], acc[mf][nf][1]);
            *(float2*)(C + (size_t)(r0 + 8) * N + n0) = make_float2(acc[mf][nf][2], acc[mf][nf][3]);
        }
    }
}

// ---------------- rmsnorm + rope for Q -> bf16 hi/lo -----------------------
__global__ __launch_bounds__(128) void qnorm_rope(
    const float* __restrict__ QG, const float* __restrict__ w,
    const float* __restrict__ cosT, const float* __restrict__ sinT,
    __nv_bfloat16* __restrict__ Qh, __nv_bfloat16* __restrict__ Ql)
{
    const int s = blockIdx.x, h = blockIdx.y, b = blockIdx.z;
    const int d = threadIdx.x;
    const float* src = QG + (((size_t)(b * Sn + s) * Hn + h) * 2 * HD);
    float x = src[d];
    float ss = x * x;
    #pragma unroll
    for (int o = 16; o > 0; o >>= 1) ss += __shfl_xor_sync(0xffffffffu, ss, o);
    __shared__ float wsum[4];
    if ((d & 31) == 0) wsum[d >> 5] = ss;
    __syncthreads();
    float tot = wsum[0] + wsum[1] + wsum[2] + wsum[3];
    float inv = rsqrtf(tot * (1.0f / HD) + EPSf);
    float n = x * inv * (1.0f + w[d]);
    __shared__ float nb[HD];
    nb[d] = n;
    __syncthreads();
    float c  = cosT[(size_t)s * HD + d];
    float sn = sinT[(size_t)s * HD + d];
    float rot = (d < HD / 2) ? -nb[d + HD / 2] : nb[d - HD / 2];
    float y = n * c + rot * sn;
    __nv_bfloat16 hh = __float2bfloat16(y);
    const size_t dst = ((size_t)(b * Hn + h) * Sn + s) * HD + d;
    Qh[dst] = hh;
    Ql[dst] = __float2bfloat16(y - __bfloat162float(hh));
}

// ---------------- rmsnorm + rope for K -> hi/lo, plus V split --------------
// reads combined KV buffer: row = [K(512) | V(512)]
__global__ __launch_bounds__(128) void knorm_rope_vsplit(
    const float* __restrict__ KV,
    const float* __restrict__ w,
    const float* __restrict__ cosT, const float* __restrict__ sinT,
    __nv_bfloat16* __restrict__ Kh, __nv_bfloat16* __restrict__ Kl,
    __nv_bfloat16* __restrict__ Vh, __nv_bfloat16* __restrict__ Vl)
{
    const int s = blockIdx.x, g = blockIdx.y, b = blockIdx.z;
    const int d = threadIdx.x;
    const float* row = KV + (size_t)(b * Sn + s) * (2 * Gn * HD) + g * HD;
    float x = row[d];
    float ss = x * x;
    #pragma unroll
    for (int o = 16; o > 0; o >>= 1) ss += __shfl_xor_sync(0xffffffffu, ss, o);
    __shared__ float wsum[4];
    if ((d & 31) == 0) wsum[d >> 5] = ss;
    __syncthreads();
    float tot = wsum[0] + wsum[1] + wsum[2] + wsum[3];
    float inv = rsqrtf(tot * (1.0f / HD) + EPSf);
    float n = x * inv * (1.0f + w[d]);
    __shared__ float nb[HD];
    nb[d] = n;
    __syncthreads();
    float c  = cosT[(size_t)s * HD + d];
    float sn = sinT[(size_t)s * HD + d];
    float rot = (d < HD / 2) ? -nb[d + HD / 2] : nb[d - HD / 2];
    float y = n * c + rot * sn;
    const size_t dst = ((size_t)(b * Gn + g) * Sn + s) * HD + d;
    __nv_bfloat16 kh = __float2bfloat16(y);
    Kh[dst] = kh;
    Kl[dst] = __float2bfloat16(y - __bfloat162float(kh));
    float v = row[Gn * HD + d];
    __nv_bfloat16 vh = __float2bfloat16(v);
    Vh[dst] = vh;
    Vl[dst] = __float2bfloat16(v - __bfloat162float(vh));
}

// ================= HMMA causal flash attention + sigmoid gate ==============
// BQ=128 (8 warps x m16), BK=64, HD=128. 3-term split on QK^T and PV.
// Epilogue writes bf16 hi/lo Ctx directly (fused fsplit).
#define AT_LDS  136
#define Q_ELE   (128 * AT_LDS)
#define KT_ELE  (64 * AT_LDS)
#define KVSTAGE_ELE (4 * KT_ELE)
#define ATT_SMEM ((2 * Q_ELE + 2 * KVSTAGE_ELE) * 2)   // 208896 bytes
#define KV_BYTES (4 * 64 * 256)                         // 65536
#define CSC 0.12751666806979654f    // (1/sqrt(128)) * log2(e)
#define NEGINF __int_as_float(0xff800000)

__device__ __forceinline__ void kv_load_bulk(
    uint32_t smb, int stage, uint32_t mbar,
    const __nv_bfloat16* kh, const __nv_bfloat16* kl,
    const __nv_bfloat16* vh, const __nv_bfloat16* vl, int tid)
{
    const uint32_t base = smb + (2 * Q_ELE + stage * KVSTAGE_ELE) * 2;
    const int tile = tid >> 6;      // 0..3
    const int row  = tid & 63;
    const __nv_bfloat16* src =
        (tile == 0 ? kh : tile == 1 ? kl : tile == 2 ? vh : vl) + (size_t)row * HD;
    cpbulk(base + (uint32_t)tile * (KT_ELE * 2) + (uint32_t)row * (AT_LDS * 2),
           src, 256, mbar);
}

__global__ __launch_bounds__(256, 1) void attn_mma(
    const __nv_bfloat16* __restrict__ Qh, const __nv_bfloat16* __restrict__ Ql,
    const __nv_bfloat16* __restrict__ Kh, const __nv_bfloat16* __restrict__ Kl,
    const __nv_bfloat16* __restrict__ Vh, const __nv_bfloat16* __restrict__ Vl,
    const float* __restrict__ QG,
    __nv_bfloat16* __restrict__ Cxh, __nv_bfloat16* __restrict__ Cxl)
{
    extern __shared__ __nv_bfloat16 smem_bf[];
    __shared__ uint64_t amb[2];
    const uint32_t smb = smem_u32(smem_bf);
    const uint32_t m0 = smem_u32(&amb[0]), m1 = smem_u32(&amb[1]);
    const int qi = blockIdx.x, h = blockIdx.y, b = blockIdx.z;
    const int g  = h / GROUPn;
    const int tid = threadIdx.x, lane = tid & 31, w = tid >> 5;

    const __nv_bfloat16* gQh = Qh + ((size_t)(b * Hn + h) * Sn + (size_t)qi * 128) * HD;
    const __nv_bfloat16* gQl = Ql + ((size_t)(b * Hn + h) * Sn + (size_t)qi * 128) * HD;
    const __nv_bfloat16* gKh = Kh + ((size_t)(b * Gn + g) * Sn) * HD;
    const __nv_bfloat16* gKl = Kl + ((size_t)(b * Gn + g) * Sn) * HD;
    const __nv_bfloat16* gVh = Vh + ((size_t)(b * Gn + g) * Sn) * HD;
    const __nv_bfloat16* gVl = Vl + ((size_t)(b * Gn + g) * Sn) * HD;

    // load Q hi/lo into smem (128 x 128)
    #pragma unroll
    for (int i = 0; i < 8; i++) {
        int u = tid + i * 256;
        int row = u >> 4, c8 = (u & 15) * 8;
        *(uint4*)(smem_bf + row * AT_LDS + c8)         = *(const uint4*)(gQh + (size_t)row * HD + c8);
        *(uint4*)(smem_bf + Q_ELE + row * AT_LDS + c8) = *(const uint4*)(gQl + (size_t)row * HD + c8);
    }
    if (tid == 0) { MBAR_INIT(m0, 1); MBAR_INIT(m1, 1); }
    __syncthreads();   // mbar init + Q visible

    float m1s = NEGINF, m2s = NEGINF, l1 = 0.f, l2 = 0.f;
    float oacc[16][4];
    #pragma unroll
    for (int nf = 0; nf < 16; nf++)
        #pragma unroll
        for (int k = 0; k < 4; k++) oacc[nf][k] = 0.f;

    const int r1rel = w * 16 + (lane >> 2);   // 0..127
    const int r1g = qi * 128 + r1rel;
    const int r2g = r1g + 8;

    if (tid == 0) MBAR_EXPECT(m0, KV_BYTES);
    kv_load_bulk(smb, 0, m0, gKh, gKl, gVh, gVl, tid);
    int ph0 = 0, ph1 = 0;

    const int ntiles = 2 * qi + 2;
    for (int t = 0; t < ntiles; t++) {
        if (t + 1 < ntiles) {
            const uint32_t mn = ((t + 1) & 1) ? m1 : m0;
            if (tid == 0) MBAR_EXPECT(mn, KV_BYTES);
            kv_load_bulk(smb, (t + 1) & 1, mn,
                         gKh + (size_t)(t + 1) * 64 * HD, gKl + (size_t)(t + 1) * 64 * HD,
                         gVh + (size_t)(t + 1) * 64 * HD, gVl + (size_t)(t + 1) * 64 * HD, tid);
        }
        if ((t & 1) == 0) { MBAR_WAIT(m0, ph0); ph0 ^= 1; }
        else             { MBAR_WAIT(m1, ph1); ph1 ^= 1; }

        const uint32_t kb = smb + (2 * Q_ELE + (t & 1) * KVSTAGE_ELE) * 2;

        // ---- scores: S = Q K^T (3-term split) ----
        float sacc[8][4];
        #pragma unroll
        for (int j = 0; j < 8; j++)
            #pragma unroll
            for (int k = 0; k < 4; k++) sacc[j][k] = 0.f;

        #pragma unroll
        for (int kq = 0; kq < 8; kq++) {
            uint32_t ah[4], al[4];
            const uint32_t qaddr = smb +
                (uint32_t)((w * 16 + (lane & 15)) * AT_LDS + ((lane >> 4) << 3) + kq * 16) * 2;
            ldsm_x4(ah, qaddr);
            ldsm_x4(al, qaddr + Q_ELE * 2);
            #pragma unroll
            for (int n16 = 0; n16 < 4; n16++) {
                uint32_t bh[4], bl[4];
                const uint32_t kaddr = kb +
                    (uint32_t)((n16 * 16 + (lane & 7) + ((lane >> 4) << 3)) * AT_LDS
                               + (((lane >> 3) & 1) << 3) + kq * 16) * 2;
                ldsm_x4(bh, kaddr);
                ldsm_x4(bl, kaddr + KT_ELE * 2);
                mma16816(sacc[2 * n16],     ah, bh);
                mma16816(sacc[2 * n16 + 1], ah, bh + 2);
                mma16816(sacc[2 * n16],     ah, bl);
                mma16816(sacc[2 * n16 + 1], ah, bl + 2);
                mma16816(sacc[2 * n16],     al, bh);
                mma16816(sacc[2 * n16 + 1], al, bh + 2);
            }
        }

        // ---- online softmax (log2 domain) ----
        const bool needmask = (t >= 2 * qi);
        float mt1 = m1s, mt2 = m2s;
        #pragma unroll
        for (int j = 0; j < 8; j++) {
            const int c0 = t * 64 + j * 8 + (lane & 3) * 2;
            #pragma unroll
            for (int k = 0; k < 4; k++) sacc[j][k] *= CSC;
            if (needmask) {
                if (c0     > r1g) sacc[j][0] = NEGINF;
                if (c0 + 1 > r1g) sacc[j][1] = NEGINF;
                if (c0     > r2g) sacc[j][2] = NEGINF;
                if (c0 + 1 > r2g) sacc[j][3] = NEGINF;
            }
            mt1 = fmaxf(mt1, fmaxf(sacc[j][0], sacc[j][1]));
            mt2 = fmaxf(mt2, fmaxf(sacc[j][2], sacc[j][3]));
        }
        mt1 = fmaxf(mt1, __shfl_xor_sync(0xffffffffu, mt1, 1));
        mt1 = fmaxf(mt1, __shfl_xor_sync(0xffffffffu, mt1, 2));
        mt2 = fmaxf(mt2, __shfl_xor_sync(0xffffffffu, mt2, 1));
        mt2 = fmaxf(mt2, __shfl_xor_sync(0xffffffffu, mt2, 2));
        const float f1 = ex2f(m1s - mt1), f2 = ex2f(m2s - mt2);
        m1s = mt1; m2s = mt2;
        float s1 = 0.f, s2 = 0.f;
        #pragma unroll
        for (int j = 0; j < 8; j++) {
            sacc[j][0] = ex2f(sacc[j][0] - mt1);
            sacc[j][1] = ex2f(sacc[j][1] - mt1);
            sacc[j][2] = ex2f(sacc[j][2] - mt2);
            sacc[j][3] = ex2f(sacc[j][3] - mt2);
            s1 += sacc[j][0] + sacc[j][1];
            s2 += sacc[j][2] + sacc[j][3];
        }
        l1 = l1 * f1 + s1;
        l2 = l2 * f2 + s2;
        #pragma unroll
        for (int nf = 0; nf < 16; nf++) {
            oacc[nf][0] *= f1; oacc[nf][1] *= f1;
            oacc[nf][2] *= f2; oacc[nf][3] *= f2;
        }

        // ---- PV: out += P V (3-term split, P repacked in registers) ----
        #pragma unroll
        for (int kk = 0; kk < 4; kk++) {
            uint32_t aph[4], apl[4];
            #pragma unroll
            for (int half = 0; half < 2; half++) {
                const float p0 = sacc[2 * kk + half][0], p1 = sacc[2 * kk + half][1];
                const float p2 = sacc[2 * kk + half][2], p3 = sacc[2 * kk + half][3];
                const uint32_t h01 = packbf2(p0, p1);
                const uint32_t h23 = packbf2(p2, p3);
                aph[2 * half]     = h01;
                aph[2 * half + 1] = h23;
                apl[2 * half]     = packbf2(p0 - __uint_as_float(h01 << 16),
                                            p1 - __uint_as_float(h01 & 0xffff0000u));
                apl[2 * half + 1] = packbf2(p2 - __uint_as_float(h23 << 16),
                                            p3 - __uint_as_float(h23 & 0xffff0000u));
            }
            uint32_t a_h[4] = { aph[0], aph[1], aph[2], aph[3] };
            uint32_t a_l[4] = { apl[0], apl[1], apl[2], apl[3] };
            #pragma unroll
            for (int dc = 0; dc < 8; dc++) {
                uint32_t bvh[4], bvl[4];
                const uint32_t vaddr = kb + 2 * KT_ELE * 2 +
                    (uint32_t)((kk * 16 + (lane & 15)) * AT_LDS + dc * 16 + ((lane >> 4) << 3)) * 2;
                ldsm_x4t(bvh, vaddr);
                ldsm_x4t(bvl, vaddr + KT_ELE * 2);
                mma16816(oacc[2 * dc],     a_h, bvh);
                mma16816(oacc[2 * dc + 1], a_h, bvh + 2);
                mma16816(oacc[2 * dc],     a_h, bvl);
                mma16816(oacc[2 * dc + 1], a_h, bvl + 2);
                mma16816(oacc[2 * dc],     a_l, bvh);
                mma16816(oacc[2 * dc + 1], a_l, bvh + 2);
            }
        }
        __syncthreads();   // release KV buffer for reissue
    }

    // ---- epilogue: /l, * sigmoid(gate), write bf16 hi/lo Ctx ----
    l1 += __shfl_xor_sync(0xffffffffu, l1, 1);
    l1 += __shfl_xor_sync(0xffffffffu, l1, 2);
    l2 += __shfl_xor_sync(0xffffffffu, l2, 1);
    l2 += __shfl_xor_sync(0xffffffffu, l2, 2);
    const float inv1 = 1.0f / l1, inv2 = 1.0f / l2;
    #pragma unroll
    for (int nf = 0; nf < 16; nf++) {
        const int dim = nf * 8 + (lane & 3) * 2;
        #pragma unroll
        for (int rr = 0; rr < 2; rr++) {
            const int q = rr ? r2g : r1g;
            const float invl = rr ? inv2 : inv1;
            const float a0 = oacc[nf][2 * rr], a1 = oacc[nf][2 * rr + 1];
            const float2 gt = *(const float2*)(QG + (((size_t)(b * Sn + q) * Hn + h) * 2 * HD) + HD + dim);
            const float v0 = a0 * invl * (1.0f / (1.0f + expf(-gt.x)));
            const float v1 = a1 * invl * (1.0f / (1.0f + expf(-gt.y)));
            const __nv_bfloat16 h0 = __float2bfloat16(v0);
            const __nv_bfloat16 h1 = __float2bfloat16(v1);
            const size_t off = (size_t)(b * Sn + q) * DOUT + h * HD + dim;
            *(__nv_bfloat162*)(Cxh + off) = __nv_bfloat162(h0, h1);
            *(__nv_bfloat162*)(Cxl + off) =
                __nv_bfloat162(__float2bfloat16(v0 - __bfloat162float(h0)),
                               __float2bfloat16(v1 - __bfloat162float(h1)));
        }
    }
}

// ---------------------------- launcher -------------------------------------
extern "C" void kernel_launch(void* const* d_in, const int* in_sizes, int n_in,
                              void* d_out, int out_size)
{
    const float* x    = (const float*)d_in[0];
    const float* Wq   = (const float*)d_in[1];
    const float* Wk   = (const float*)d_in[2];
    const float* Wv   = (const float*)d_in[3];
    const float* Wo   = (const float*)d_in[4];
    const float* qw   = (const float*)d_in[5];
    const float* kw   = (const float*)d_in[6];
    const float* cosT = (const float*)d_in[7];
    const float* sinT = (const float*)d_in[8];
    float* out = (float*)d_out;

    float *QG, *KV;
    cudaGetSymbolAddress((void**)&QG, g_QG);
    cudaGetSymbolAddress((void**)&KV, g_KV);

    __nv_bfloat16 *Qhp, *Qlp, *Khp, *Klp, *Vhp, *Vlp;
    cudaGetSymbolAddress((void**)&Qhp, g_Qh);
    cudaGetSymbolAddress((void**)&Qlp, g_Ql);
    cudaGetSymbolAddress((void**)&Khp, g_Kh);
    cudaGetSymbolAddress((void**)&Klp, g_Kl);
    cudaGetSymbolAddress((void**)&Vhp, g_Vh);
    cudaGetSymbolAddress((void**)&Vlp, g_Vl);

    __nv_bfloat16 *xh, *xl, *Wqh, *Wql, *Wkvh, *Wkvl, *Woh, *Wol, *Cxh, *Cxl;
    cudaGetSymbolAddress((void**)&xh,   g_xh);
    cudaGetSymbolAddress((void**)&xl,   g_xl);
    cudaGetSymbolAddress((void**)&Wqh,  g_Wqh);
    cudaGetSymbolAddress((void**)&Wql,  g_Wql);
    cudaGetSymbolAddress((void**)&Wkvh, g_Wkvh);
    cudaGetSymbolAddress((void**)&Wkvl, g_Wkvl);
    cudaGetSymbolAddress((void**)&Woh,  g_Woh);
    cudaGetSymbolAddress((void**)&Wol,  g_Wol);
    cudaGetSymbolAddress((void**)&Cxh,  g_Cxh);
    cudaGetSymbolAddress((void**)&Cxl,  g_Cxl);

    cudaFuncSetAttribute(gemm_tc, cudaFuncAttributeMaxDynamicSharedMemorySize, GEMM_SMEM);
    cudaFuncSetAttribute(attn_mma, cudaFuncAttributeMaxDynamicSharedMemorySize, ATT_SMEM);

    const int M = Mrows;  // 4096
    const int NKV = 2 * Gn * HD;  // 1024

    // split x, transpose+split weights (Wk and Wv packed into one [1024][2048])
    fsplit<<<(M * DIN / 4 + 255) / 256, 256>>>(x, xh, xl, M * DIN);
    tsplit<<<dim3((2 * DOUT) / 32, DIN / 32), dim3(32, 8)>>>(Wq, Wqh, Wql, DIN, 2 * DOUT);
    tsplit<<<dim3((Gn * HD) / 32, DIN / 32), dim3(32, 8)>>>(Wk, Wkvh, Wkvl, DIN, Gn * HD);
    tsplit<<<dim3((Gn * HD) / 32, DIN / 32), dim3(32, 8)>>>(
        Wv, Wkvh + (size_t)(Gn * HD) * DIN, Wkvl + (size_t)(Gn * HD) * DIN, DIN, Gn * HD);
    tsplit<<<dim3(DIN / 32, DOUT / 32), dim3(32, 8)>>>(Wo, Woh, Wol, DOUT, DIN);

    // projections (HMMA split-bf16, bulk-copy loads)
    gemm_tc<<<dim3((2 * DOUT) / 128, M / 256), 256, GEMM_SMEM>>>(
        xh, xl, Wqh, Wql, QG, M, 2 * DOUT, DIN);
    gemm_tc<<<dim3(NKV / 128, M / 256), 256, GEMM_SMEM>>>(
        xh, xl, Wkvh, Wkvl, KV, M, NKV, DIN);

    // norm + rope -> bf16 hi/lo
    qnorm_rope<<<dim3(Sn, Hn, Bn), 128>>>(QG, qw, cosT, sinT, Qhp, Qlp);
    knorm_rope_vsplit<<<dim3(Sn, Gn, Bn), 128>>>(KV, kw, cosT, sinT,
                                                 Khp, Klp, Vhp, Vlp);

    // HMMA causal attention + gate (BQ=128), fused bf16 split epilogue
    attn_mma<<<dim3(Sn / 128, Hn, Bn), 256, ATT_SMEM>>>(
        Qhp, Qlp, Khp, Klp, Vhp, Vlp, QG, Cxh, Cxl);

    // output projection
    gemm_tc<<<dim3(DIN / 128, M / 256), 256, GEMM_SMEM>>>(
        Cxh, Cxl, Woh, Wol, out, M, DIN, DOUT);
}

// round 7
// speedup vs baseline: 1.5860x; 1.5860x over previous
#include <cuda_runtime.h>
#include <cuda_bf16.h>
#include <math.h>
#include <stdint.h>

#define Bn    2
#define Sn    2048
#define DIN   2048
#define Hn    16
#define Gn    4
#define HD    128
#define DOUT  2048
#define GROUPn 4          // H / G
#define EPSf  1e-6f
#define Mrows (Bn*Sn)     // 4096

// ---------------- scratch (device globals; no allocation allowed) ----------
__device__ float g_QG  [(size_t)Bn*Sn*Hn*2*HD];   // [b,s,h,2*HD]  (q | gate)
__device__ float g_KV  [(size_t)Bn*Sn*(2*Gn*HD)]; // [b,s, K(512) | V(512)]

// bf16 hi/lo attention operands
__device__ __nv_bfloat16 g_Qh[(size_t)Bn*Hn*Sn*HD];
__device__ __nv_bfloat16 g_Ql[(size_t)Bn*Hn*Sn*HD];
__device__ __nv_bfloat16 g_Kh[(size_t)Bn*Gn*Sn*HD];
__device__ __nv_bfloat16 g_Kl[(size_t)Bn*Gn*Sn*HD];
__device__ __nv_bfloat16 g_Vh[(size_t)Bn*Gn*Sn*HD];
__device__ __nv_bfloat16 g_Vl[(size_t)Bn*Gn*Sn*HD];

// bf16 split scratch for GEMMs
__device__ __nv_bfloat16 g_xh  [(size_t)Mrows*DIN];
__device__ __nv_bfloat16 g_xl  [(size_t)Mrows*DIN];
__device__ __nv_bfloat16 g_Wqh [(size_t)(2*DOUT)*DIN];
__device__ __nv_bfloat16 g_Wql [(size_t)(2*DOUT)*DIN];
__device__ __nv_bfloat16 g_Wkvh[(size_t)(2*Gn*HD)*DIN];  // [K(512)|V(512)][2048]
__device__ __nv_bfloat16 g_Wkvl[(size_t)(2*Gn*HD)*DIN];
__device__ __nv_bfloat16 g_Woh [(size_t)DIN*DOUT];
__device__ __nv_bfloat16 g_Wol [(size_t)DIN*DOUT];
__device__ __nv_bfloat16 g_Cxh [(size_t)Mrows*DOUT];
__device__ __nv_bfloat16 g_Cxl [(size_t)Mrows*DOUT];

// ======================= PTX helpers (compute_103 baseline only) ==========
__device__ __forceinline__ uint32_t smem_u32(const void* p) {
    uint32_t a;
    asm("{ .reg .u64 t; cvta.to.shared.u64 t, %1; cvt.u32.u64 %0, t; }" : "=r"(a) : "l"(p));
    return a;
}
__device__ __forceinline__ void cp16(uint32_t s, const void* g) {
    asm volatile("cp.async.cg.shared.global [%0], [%1], 16;" :: "r"(s), "l"(g));
}
#define CP_COMMIT() asm volatile("cp.async.commit_group;" ::: "memory")
#define CP_WAIT(n)  asm volatile("cp.async.wait_group %0;" :: "n"(n) : "memory")

__device__ __forceinline__ void ldsm_x4(uint32_t* r, uint32_t addr) {
    asm volatile("ldmatrix.sync.aligned.m8n8.x4.shared.b16 {%0,%1,%2,%3}, [%4];"
        : "=r"(r[0]), "=r"(r[1]), "=r"(r[2]), "=r"(r[3]) : "r"(addr));
}
__device__ __forceinline__ void ldsm_x4t(uint32_t* r, uint32_t addr) {
    asm volatile("ldmatrix.sync.aligned.m8n8.x4.trans.shared.b16 {%0,%1,%2,%3}, [%4];"
        : "=r"(r[0]), "=r"(r[1]), "=r"(r[2]), "=r"(r[3]) : "r"(addr));
}
__device__ __forceinline__ void mma16816(float* d, const uint32_t* a, const uint32_t* b) {
    asm volatile(
        "mma.sync.aligned.m16n8k16.row.col.f32.bf16.bf16.f32 "
        "{%0,%1,%2,%3}, {%4,%5,%6,%7}, {%8,%9}, {%0,%1,%2,%3};"
        : "+f"(d[0]), "+f"(d[1]), "+f"(d[2]), "+f"(d[3])
        : "r"(a[0]), "r"(a[1]), "r"(a[2]), "r"(a[3]), "r"(b[0]), "r"(b[1]));
}
__device__ __forceinline__ float ex2f(float x) {
    float r; asm("ex2.approx.f32 %0, %1;" : "=f"(r) : "f"(x)); return r;
}
__device__ __forceinline__ uint32_t packbf2(float lo, float hi) {
    uint32_t r; asm("cvt.rn.bf16x2.f32 %0, %1, %2;" : "=r"(r) : "f"(hi), "f"(lo)); return r;
}

// ======================= split / transpose-split ==========================
__global__ __launch_bounds__(256) void fsplit(const float* __restrict__ in,
                                              __nv_bfloat16* __restrict__ h,
                                              __nv_bfloat16* __restrict__ l, int n)
{
    int i = (blockIdx.x * 256 + threadIdx.x) * 4;
    if (i >= n) return;
    float4 v = *(const float4*)(in + i);
    __nv_bfloat16 h0 = __float2bfloat16(v.x), h1 = __float2bfloat16(v.y);
    __nv_bfloat16 h2 = __float2bfloat16(v.z), h3 = __float2bfloat16(v.w);
    __nv_bfloat16 l0 = __float2bfloat16(v.x - __bfloat162float(h0));
    __nv_bfloat16 l1 = __float2bfloat16(v.y - __bfloat162float(h1));
    __nv_bfloat16 l2 = __float2bfloat16(v.z - __bfloat162float(h2));
    __nv_bfloat16 l3 = __float2bfloat16(v.w - __bfloat162float(h3));
    *(__nv_bfloat162*)(h + i)     = __nv_bfloat162(h0, h1);
    *(__nv_bfloat162*)(h + i + 2) = __nv_bfloat162(h2, h3);
    *(__nv_bfloat162*)(l + i)     = __nv_bfloat162(l0, l1);
    *(__nv_bfloat162*)(l + i + 2) = __nv_bfloat162(l2, l3);
}

// W[K,N] fp32 -> Th/Tl[N,K] bf16 (transpose + split)
__global__ __launch_bounds__(256) void tsplit(const float* __restrict__ W,
                                              __nv_bfloat16* __restrict__ Th,
                                              __nv_bfloat16* __restrict__ Tl,
                                              int K, int N)
{
    __shared__ float t[32][33];
    const int n0 = blockIdx.x * 32, k0 = blockIdx.y * 32;
    const int tx = threadIdx.x, ty = threadIdx.y;  // (32, 8)
    #pragma unroll
    for (int r = 0; r < 4; r++)
        t[ty + r * 8][tx] = W[(size_t)(k0 + ty + r * 8) * N + n0 + tx];
    __syncthreads();
    #pragma unroll
    for (int r = 0; r < 4; r++) {
        int n = n0 + ty + r * 8, k = k0 + tx;
        float v = t[tx][ty + r * 8];
        __nv_bfloat16 h = __float2bfloat16(v);
        __nv_bfloat16 l = __float2bfloat16(v - __bfloat162float(h));
        Th[(size_t)n * K + k] = h;
        Tl[(size_t)n * K + k] = l;
    }
}

// ======================= HMMA split-bf16 GEMM (256x128, 3-stage) ===========
// C[M,N] = A[M,K] * B^T, A (hi/lo) [M,K], Bt (hi/lo) [N,K], K-major bf16.
// 256 threads (8 warps as 4m x 2n), warp tile 64x64, K-chunk 32.
#define GBK    32
#define LDS    40
#define ATILEB (256 * LDS * 2)   // 20480 B
#define BTILEB (128 * LDS * 2)   // 10240 B
#define STAGEB (2 * ATILEB + 2 * BTILEB)  // 61440 B
#define NSTAGE 3
#define GEMM_SMEM (NSTAGE * STAGEB)       // 184320 B
#define OFF_AL  ATILEB
#define OFF_BH  (2 * ATILEB)
#define OFF_BL  (2 * ATILEB + BTILEB)

__device__ __forceinline__ void load_stage(
    uint32_t smb, int stage,
    const __nv_bfloat16* __restrict__ pAh, const __nv_bfloat16* __restrict__ pAl,
    const __nv_bfloat16* __restrict__ pBh, const __nv_bfloat16* __restrict__ pBl,
    int K, int kc, int tid)
{
    const uint32_t sb = smb + stage * STAGEB;
    // A: 256 rows x 32 cols hi+lo
    #pragma unroll
    for (int i = 0; i < 4; i++) {
        const int u = tid + i * 256;
        const int row = u >> 2, col = (u & 3) * 8;
        const uint32_t so = (uint32_t)(row * LDS + col) * 2;
        const size_t g = (size_t)row * K + kc + col;
        cp16(sb + so,          pAh + g);
        cp16(sb + OFF_AL + so, pAl + g);
    }
    // B: 128 rows x 32 cols hi+lo
    #pragma unroll
    for (int i = 0; i < 2; i++) {
        const int u = tid + i * 256;
        const int row = u >> 2, col = (u & 3) * 8;
        const uint32_t so = (uint32_t)(row * LDS + col) * 2;
        const size_t g = (size_t)row * K + kc + col;
        cp16(sb + OFF_BH + so, pBh + g);
        cp16(sb + OFF_BL + so, pBl + g);
    }
}

__global__ __launch_bounds__(256, 1) void gemm_tc(
    const __nv_bfloat16* __restrict__ Ah, const __nv_bfloat16* __restrict__ Al,
    const __nv_bfloat16* __restrict__ Bh, const __nv_bfloat16* __restrict__ Bl,
    float* __restrict__ C, int M, int N, int K)
{
    extern __shared__ char sm[];
    const uint32_t smb = smem_u32(sm);
    const int tid  = threadIdx.x;
    const int wid  = tid >> 5, lane = tid & 31;
    const int wm   = wid & 3;           // 4 m-warps x 64 rows
    const int wn   = wid >> 2;          // 2 n-warps x 64 cols
    const int mbr  = blockIdx.y * 256, nbr = blockIdx.x * 128;

    const __nv_bfloat16* pAh = Ah + (size_t)mbr * K;
    const __nv_bfloat16* pAl = Al + (size_t)mbr * K;
    const __nv_bfloat16* pBh = Bh + (size_t)nbr * K;
    const __nv_bfloat16* pBl = Bl + (size_t)nbr * K;

    float acc[4][8][4];
    #pragma unroll
    for (int i = 0; i < 4; i++)
        #pragma unroll
        for (int j = 0; j < 8; j++)
            #pragma unroll
            for (int k = 0; k < 4; k++) acc[i][j][k] = 0.f;

    const uint32_t aoff = (uint32_t)((wm * 64 + (lane & 15)) * LDS + ((lane >> 4) * 8)) * 2;
    const uint32_t boff = (uint32_t)((wn * 64 + (lane & 7) + ((lane >> 4) << 3)) * LDS
                                     + (((lane >> 3) & 1) * 8)) * 2;

    const int NC = K / GBK;
    load_stage(smb, 0, pAh, pAl, pBh, pBl, K, 0, tid);
    CP_COMMIT();
    if (NC > 1) {
        load_stage(smb, 1, pAh, pAl, pBh, pBl, K, GBK, tid);
        CP_COMMIT();
    }

    int st_idx = 0;
    for (int c = 0; c < NC; c++) {
        if (c + 2 < NC) {
            int ns = st_idx + 2; if (ns >= NSTAGE) ns -= NSTAGE;
            load_stage(smb, ns, pAh, pAl, pBh, pBl, K, (c + 2) * GBK, tid);
            CP_COMMIT();
            CP_WAIT(2);
        } else if (c + 1 < NC) {
            CP_WAIT(1);
        } else {
            CP_WAIT(0);
        }
        __syncthreads();

        const uint32_t st = smb + st_idx * STAGEB;
        #pragma unroll
        for (int ks = 0; ks < 2; ks++) {
            const uint32_t kb = ks * 32;
            uint32_t bh[16], bl[16];
            #pragma unroll
            for (int n16 = 0; n16 < 4; n16++) {
                ldsm_x4(bh + 4 * n16, st + OFF_BH + boff + n16 * (16 * LDS * 2) + kb);
                ldsm_x4(bl + 4 * n16, st + OFF_BL + boff + n16 * (16 * LDS * 2) + kb);
            }
            #pragma unroll
            for (int mf = 0; mf < 4; mf++) {
                uint32_t ah[4], al[4];
                ldsm_x4(ah, st + aoff + mf * (16 * LDS * 2) + kb);
                ldsm_x4(al, st + OFF_AL + aoff + mf * (16 * LDS * 2) + kb);
                // term-major: same-acc MMAs are 8 apart
                #pragma unroll
                for (int nf = 0; nf < 8; nf++)
                    mma16816(acc[mf][nf], ah, &bh[(nf >> 1) * 4 + (nf & 1) * 2]);
                #pragma unroll
                for (int nf = 0; nf < 8; nf++)
                    mma16816(acc[mf][nf], ah, &bl[(nf >> 1) * 4 + (nf & 1) * 2]);
                #pragma unroll
                for (int nf = 0; nf < 8; nf++)
                    mma16816(acc[mf][nf], al, &bh[(nf >> 1) * 4 + (nf & 1) * 2]);
            }
        }
        __syncthreads();   // all warps done reading stage before it is refilled
        if (++st_idx == NSTAGE) st_idx = 0;
    }

    #pragma unroll
    for (int mf = 0; mf < 4; mf++) {
        const int r0 = mbr + wm * 64 + mf * 16 + (lane >> 2);
        #pragma unroll
        for (int nf = 0; nf < 8; nf++) {
            const int n0 = nbr + wn * 64 + nf * 8 + (lane & 3) * 2;
            *(float2*)(C + (size_t)r0 * N + n0)       = make_float2(acc[mf][nf][0], acc[mf][nf][1]);
            *(float2*)(C + (size_t)(r0 + 8) * N + n0) = make_float2(acc[mf][nf][2], acc[mf][nf][3]);
        }
    }
}

// ---------------- rmsnorm + rope for Q -> bf16 hi/lo -----------------------
__global__ __launch_bounds__(128) void qnorm_rope(
    const float* __restrict__ QG, const float* __restrict__ w,
    const float* __restrict__ cosT, const float* __restrict__ sinT,
    __nv_bfloat16* __restrict__ Qh, __nv_bfloat16* __restrict__ Ql)
{
    const int s = blockIdx.x, h = blockIdx.y, b = blockIdx.z;
    const int d = threadIdx.x;
    const float* src = QG + (((size_t)(b * Sn + s) * Hn + h) * 2 * HD);
    float x = src[d];
    float ss = x * x;
    #pragma unroll
    for (int o = 16; o > 0; o >>= 1) ss += __shfl_xor_sync(0xffffffffu, ss, o);
    __shared__ float wsum[4];
    if ((d & 31) == 0) wsum[d >> 5] = ss;
    __syncthreads();
    float tot = wsum[0] + wsum[1] + wsum[2] + wsum[3];
    float inv = rsqrtf(tot * (1.0f / HD) + EPSf);
    float n = x * inv * (1.0f + w[d]);
    __shared__ float nb[HD];
    nb[d] = n;
    __syncthreads();
    float c  = cosT[(size_t)s * HD + d];
    float sn = sinT[(size_t)s * HD + d];
    float rot = (d < HD / 2) ? -nb[d + HD / 2] : nb[d - HD / 2];
    float y = n * c + rot * sn;
    __nv_bfloat16 hh = __float2bfloat16(y);
    const size_t dst = ((size_t)(b * Hn + h) * Sn + s) * HD + d;
    Qh[dst] = hh;
    Ql[dst] = __float2bfloat16(y - __bfloat162float(hh));
}

// ---------------- rmsnorm + rope for K -> hi/lo, plus V split --------------
// reads combined KV buffer: row = [K(512) | V(512)]
__global__ __launch_bounds__(128) void knorm_rope_vsplit(
    const float* __restrict__ KV,
    const float* __restrict__ w,
    const float* __restrict__ cosT, const float* __restrict__ sinT,
    __nv_bfloat16* __restrict__ Kh, __nv_bfloat16* __restrict__ Kl,
    __nv_bfloat16* __restrict__ Vh, __nv_bfloat16* __restrict__ Vl)
{
    const int s = blockIdx.x, g = blockIdx.y, b = blockIdx.z;
    const int d = threadIdx.x;
    const float* row = KV + (size_t)(b * Sn + s) * (2 * Gn * HD) + g * HD;
    float x = row[d];
    float ss = x * x;
    #pragma unroll
    for (int o = 16; o > 0; o >>= 1) ss += __shfl_xor_sync(0xffffffffu, ss, o);
    __shared__ float wsum[4];
    if ((d & 31) == 0) wsum[d >> 5] = ss;
    __syncthreads();
    float tot = wsum[0] + wsum[1] + wsum[2] + wsum[3];
    float inv = rsqrtf(tot * (1.0f / HD) + EPSf);
    float n = x * inv * (1.0f + w[d]);
    __shared__ float nb[HD];
    nb[d] = n;
    __syncthreads();
    float c  = cosT[(size_t)s * HD + d];
    float sn = sinT[(size_t)s * HD + d];
    float rot = (d < HD / 2) ? -nb[d + HD / 2] : nb[d - HD / 2];
    float y = n * c + rot * sn;
    const size_t dst = ((size_t)(b * Gn + g) * Sn + s) * HD + d;
    __nv_bfloat16 kh = __float2bfloat16(y);
    Kh[dst] = kh;
    Kl[dst] = __float2bfloat16(y - __bfloat162float(kh));
    float v = row[Gn * HD + d];
    __nv_bfloat16 vh = __float2bfloat16(v);
    Vh[dst] = vh;
    Vl[dst] = __float2bfloat16(v - __bfloat162float(vh));
}

// ================= HMMA causal flash attention + sigmoid gate ==============
// BQ=128 (8 warps x m16), BK=64, HD=128. 3-term split on QK^T and PV.
// Epilogue writes bf16 hi/lo Ctx directly (fused fsplit).
#define AT_LDS  136
#define Q_ELE   (128 * AT_LDS)
#define KT_ELE  (64 * AT_LDS)
#define KVSTAGE_ELE (4 * KT_ELE)
#define ATT_SMEM ((2 * Q_ELE + 2 * KVSTAGE_ELE) * 2)   // 208896 bytes
#define CSC 0.12751666806979654f    // (1/sqrt(128)) * log2(e)
#define NEGINF __int_as_float(0xff800000)

__device__ __forceinline__ void kv_load(
    uint32_t smb, int stage,
    const __nv_bfloat16* kh, const __nv_bfloat16* kl,
    const __nv_bfloat16* vh, const __nv_bfloat16* vl, int tid)
{
    const uint32_t base = smb + (2 * Q_ELE + stage * KVSTAGE_ELE) * 2;
    #pragma unroll
    for (int i = 0; i < 4; i++) {
        int u = tid + i * 256;          // 0..1023
        int row = u >> 4, c8 = (u & 15) * 8;
        uint32_t so = (uint32_t)(row * AT_LDS + c8) * 2;
        size_t go = (size_t)row * HD + c8;
        cp16(base + 0 * KT_ELE * 2 + so, kh + go);
        cp16(base + 1 * KT_ELE * 2 + so, kl + go);
        cp16(base + 2 * KT_ELE * 2 + so, vh + go);
        cp16(base + 3 * KT_ELE * 2 + so, vl + go);
    }
}

__global__ __launch_bounds__(256, 1) void attn_mma(
    const __nv_bfloat16* __restrict__ Qh, const __nv_bfloat16* __restrict__ Ql,
    const __nv_bfloat16* __restrict__ Kh, const __nv_bfloat16* __restrict__ Kl,
    const __nv_bfloat16* __restrict__ Vh, const __nv_bfloat16* __restrict__ Vl,
    const float* __restrict__ QG,
    __nv_bfloat16* __restrict__ Cxh, __nv_bfloat16* __restrict__ Cxl)
{
    extern __shared__ __nv_bfloat16 smem_bf[];
    const uint32_t smb = smem_u32(smem_bf);
    const int qi = blockIdx.x, h = blockIdx.y, b = blockIdx.z;
    const int g  = h / GROUPn;
    const int tid = threadIdx.x, lane = tid & 31, w = tid >> 5;

    const __nv_bfloat16* gQh = Qh + ((size_t)(b * Hn + h) * Sn + (size_t)qi * 128) * HD;
    const __nv_bfloat16* gQl = Ql + ((size_t)(b * Hn + h) * Sn + (size_t)qi * 128) * HD;
    const __nv_bfloat16* gKh = Kh + ((size_t)(b * Gn + g) * Sn) * HD;
    const __nv_bfloat16* gKl = Kl + ((size_t)(b * Gn + g) * Sn) * HD;
    const __nv_bfloat16* gVh = Vh + ((size_t)(b * Gn + g) * Sn) * HD;
    const __nv_bfloat16* gVl = Vl + ((size_t)(b * Gn + g) * Sn) * HD;

    // load Q hi/lo into smem (128 x 128)
    #pragma unroll
    for (int i = 0; i < 8; i++) {
        int u = tid + i * 256;
        int row = u >> 4, c8 = (u & 15) * 8;
        *(uint4*)(smem_bf + row * AT_LDS + c8)         = *(const uint4*)(gQh + (size_t)row * HD + c8);
        *(uint4*)(smem_bf + Q_ELE + row * AT_LDS + c8) = *(const uint4*)(gQl + (size_t)row * HD + c8);
    }

    float m1s = NEGINF, m2s = NEGINF, l1 = 0.f, l2 = 0.f;
    float oacc[16][4];
    #pragma unroll
    for (int nf = 0; nf < 16; nf++)
        #pragma unroll
        for (int k = 0; k < 4; k++) oacc[nf][k] = 0.f;

    const int r1rel = w * 16 + (lane >> 2);   // 0..127
    const int r1g = qi * 128 + r1rel;
    const int r2g = r1g + 8;

    kv_load(smb, 0, gKh, gKl, gVh, gVl, tid);
    CP_COMMIT();

    const int ntiles = 2 * qi + 2;
    for (int t = 0; t < ntiles; t++) {
        if (t + 1 < ntiles) {
            kv_load(smb, (t + 1) & 1,
                    gKh + (size_t)(t + 1) * 64 * HD, gKl + (size_t)(t + 1) * 64 * HD,
                    gVh + (size_t)(t + 1) * 64 * HD, gVl + (size_t)(t + 1) * 64 * HD, tid);
            CP_COMMIT();
            CP_WAIT(1);
        } else {
            CP_WAIT(0);
        }
        __syncthreads();

        const uint32_t kb = smb + (2 * Q_ELE + (t & 1) * KVSTAGE_ELE) * 2;

        // ---- scores: S = Q K^T (3-term split, term-major) ----
        float sacc[8][4];
        #pragma unroll
        for (int j = 0; j < 8; j++)
            #pragma unroll
            for (int k = 0; k < 4; k++) sacc[j][k] = 0.f;

        #pragma unroll
        for (int kq = 0; kq < 8; kq++) {
            uint32_t ah[4], al[4], bh[16], bl[16];
            const uint32_t qaddr = smb +
                (uint32_t)((w * 16 + (lane & 15)) * AT_LDS + ((lane >> 4) << 3) + kq * 16) * 2;
            ldsm_x4(ah, qaddr);
            ldsm_x4(al, qaddr + Q_ELE * 2);
            #pragma unroll
            for (int n16 = 0; n16 < 4; n16++) {
                const uint32_t kaddr = kb +
                    (uint32_t)((n16 * 16 + (lane & 7) + ((lane >> 4) << 3)) * AT_LDS
                               + (((lane >> 3) & 1) << 3) + kq * 16) * 2;
                ldsm_x4(bh + 4 * n16, kaddr);
                ldsm_x4(bl + 4 * n16, kaddr + KT_ELE * 2);
            }
            #pragma unroll
            for (int n16 = 0; n16 < 4; n16++) {
                mma16816(sacc[2 * n16],     ah, bh + 4 * n16);
                mma16816(sacc[2 * n16 + 1], ah, bh + 4 * n16 + 2);
            }
            #pragma unroll
            for (int n16 = 0; n16 < 4; n16++) {
                mma16816(sacc[2 * n16],     ah, bl + 4 * n16);
                mma16816(sacc[2 * n16 + 1], ah, bl + 4 * n16 + 2);
            }
            #pragma unroll
            for (int n16 = 0; n16 < 4; n16++) {
                mma16816(sacc[2 * n16],     al, bh + 4 * n16);
                mma16816(sacc[2 * n16 + 1], al, bh + 4 * n16 + 2);
            }
        }

        // ---- online softmax (log2 domain) ----
        const bool needmask = (t >= 2 * qi);
        float mt1 = m1s, mt2 = m2s;
        #pragma unroll
        for (int j = 0; j < 8; j++) {
            const int c0 = t * 64 + j * 8 + (lane & 3) * 2;
            #pragma unroll
            for (int k = 0; k < 4; k++) sacc[j][k] *= CSC;
            if (needmask) {
                if (c0     > r1g) sacc[j][0] = NEGINF;
                if (c0 + 1 > r1g) sacc[j][1] = NEGINF;
                if (c0     > r2g) sacc[j][2] = NEGINF;
                if (c0 + 1 > r2g) sacc[j][3] = NEGINF;
            }
            mt1 = fmaxf(mt1, fmaxf(sacc[j][0], sacc[j][1]));
            mt2 = fmaxf(mt2, fmaxf(sacc[j][2], sacc[j][3]));
        }
        mt1 = fmaxf(mt1, __shfl_xor_sync(0xffffffffu, mt1, 1));
        mt1 = fmaxf(mt1, __shfl_xor_sync(0xffffffffu, mt1, 2));
        mt2 = fmaxf(mt2, __shfl_xor_sync(0xffffffffu, mt2, 1));
        mt2 = fmaxf(mt2, __shfl_xor_sync(0xffffffffu, mt2, 2));
        const float f1 = ex2f(m1s - mt1), f2 = ex2f(m2s - mt2);
        m1s = mt1; m2s = mt2;
        float s1 = 0.f, s2 = 0.f;
        #pragma unroll
        for (int j = 0; j < 8; j++) {
            sacc[j][0] = ex2f(sacc[j][0] - mt1);
            sacc[j][1] = ex2f(sacc[j][1] - mt1);
            sacc[j][2] = ex2f(sacc[j][2] - mt2);
            sacc[j][3] = ex2f(sacc[j][3] - mt2);
            s1 += sacc[j][0] + sacc[j][1];
            s2 += sacc[j][2] + sacc[j][3];
        }
        l1 = l1 * f1 + s1;
        l2 = l2 * f2 + s2;
        #pragma unroll
        for (int nf = 0; nf < 16; nf++) {
            oacc[nf][0] *= f1; oacc[nf][1] *= f1;
            oacc[nf][2] *= f2; oacc[nf][3] *= f2;
        }

        // ---- PV: out += P V (3-term split, dc processed in pairs) ----
        #pragma unroll
        for (int kk = 0; kk < 4; kk++) {
            uint32_t a_h[4], a_l[4];
            #pragma unroll
            for (int half = 0; half < 2; half++) {
                const float p0 = sacc[2 * kk + half][0], p1 = sacc[2 * kk + half][1];
                const float p2 = sacc[2 * kk + half][2], p3 = sacc[2 * kk + half][3];
                const uint32_t h01 = packbf2(p0, p1);
                const uint32_t h23 = packbf2(p2, p3);
                a_h[2 * half]     = h01;
                a_h[2 * half + 1] = h23;
                a_l[2 * half]     = packbf2(p0 - __uint_as_float(h01 << 16),
                                            p1 - __uint_as_float(h01 & 0xffff0000u));
                a_l[2 * half + 1] = packbf2(p2 - __uint_as_float(h23 << 16),
                                            p3 - __uint_as_float(h23 & 0xffff0000u));
            }
            #pragma unroll
            for (int dp = 0; dp < 4; dp++) {    // dc = 2dp, 2dp+1
                uint32_t bvh0[4], bvl0[4], bvh1[4], bvl1[4];
                const uint32_t va0 = kb + 2 * KT_ELE * 2 +
                    (uint32_t)((kk * 16 + (lane & 15)) * AT_LDS + (2 * dp) * 16 + ((lane >> 4) << 3)) * 2;
                const uint32_t va1 = va0 + 32;   // next dc: +16 elements
                ldsm_x4t(bvh0, va0);
                ldsm_x4t(bvl0, va0 + KT_ELE * 2);
                ldsm_x4t(bvh1, va1);
                ldsm_x4t(bvl1, va1 + KT_ELE * 2);
                // hh terms
                mma16816(oacc[4 * dp],     a_h, bvh0);
                mma16816(oacc[4 * dp + 1], a_h, bvh0 + 2);
                mma16816(oacc[4 * dp + 2], a_h, bvh1);
                mma16816(oacc[4 * dp + 3], a_h, bvh1 + 2);
                // hl terms
                mma16816(oacc[4 * dp],     a_h, bvl0);
                mma16816(oacc[4 * dp + 1], a_h, bvl0 + 2);
                mma16816(oacc[4 * dp + 2], a_h, bvl1);
                mma16816(oacc[4 * dp + 3], a_h, bvl1 + 2);
                // lh terms
                mma16816(oacc[4 * dp],     a_l, bvh0);
                mma16816(oacc[4 * dp + 1], a_l, bvh0 + 2);
                mma16816(oacc[4 * dp + 2], a_l, bvh1);
                mma16816(oacc[4 * dp + 3], a_l, bvh1 + 2);
            }
        }
        __syncthreads();   // release KV buffer for reissue
    }

    // ---- epilogue: /l, * sigmoid(gate), write bf16 hi/lo Ctx ----
    l1 += __shfl_xor_sync(0xffffffffu, l1, 1);
    l1 += __shfl_xor_sync(0xffffffffu, l1, 2);
    l2 += __shfl_xor_sync(0xffffffffu, l2, 1);
    l2 += __shfl_xor_sync(0xffffffffu, l2, 2);
    const float inv1 = 1.0f / l1, inv2 = 1.0f / l2;
    #pragma unroll
    for (int nf = 0; nf < 16; nf++) {
        const int dim = nf * 8 + (lane & 3) * 2;
        #pragma unroll
        for (int rr = 0; rr < 2; rr++) {
            const int q = rr ? r2g : r1g;
            const float invl = rr ? inv2 : inv1;
            const float a0 = oacc[nf][2 * rr], a1 = oacc[nf][2 * rr + 1];
            const float2 gt = *(const float2*)(QG + (((size_t)(b * Sn + q) * Hn + h) * 2 * HD) + HD + dim);
            const float v0 = a0 * invl * (1.0f / (1.0f + expf(-gt.x)));
            const float v1 = a1 * invl * (1.0f / (1.0f + expf(-gt.y)));
            const __nv_bfloat16 h0 = __float2bfloat16(v0);
            const __nv_bfloat16 h1 = __float2bfloat16(v1);
            const size_t off = (size_t)(b * Sn + q) * DOUT + h * HD + dim;
            *(__nv_bfloat162*)(Cxh + off) = __nv_bfloat162(h0, h1);
            *(__nv_bfloat162*)(Cxl + off) =
                __nv_bfloat162(__float2bfloat16(v0 - __bfloat162float(h0)),
                               __float2bfloat16(v1 - __bfloat162float(h1)));
        }
    }
}

// ---------------------------- launcher -------------------------------------
extern "C" void kernel_launch(void* const* d_in, const int* in_sizes, int n_in,
                              void* d_out, int out_size)
{
    const float* x    = (const float*)d_in[0];
    const float* Wq   = (const float*)d_in[1];
    const float* Wk   = (const float*)d_in[2];
    const float* Wv   = (const float*)d_in[3];
    const float* Wo   = (const float*)d_in[4];
    const float* qw   = (const float*)d_in[5];
    const float* kw   = (const float*)d_in[6];
    const float* cosT = (const float*)d_in[7];
    const float* sinT = (const float*)d_in[8];
    float* out = (float*)d_out;

    float *QG, *KV;
    cudaGetSymbolAddress((void**)&QG, g_QG);
    cudaGetSymbolAddress((void**)&KV, g_KV);

    __nv_bfloat16 *Qhp, *Qlp, *Khp, *Klp, *Vhp, *Vlp;
    cudaGetSymbolAddress((void**)&Qhp, g_Qh);
    cudaGetSymbolAddress((void**)&Qlp, g_Ql);
    cudaGetSymbolAddress((void**)&Khp, g_Kh);
    cudaGetSymbolAddress((void**)&Klp, g_Kl);
    cudaGetSymbolAddress((void**)&Vhp, g_Vh);
    cudaGetSymbolAddress((void**)&Vlp, g_Vl);

    __nv_bfloat16 *xh, *xl, *Wqh, *Wql, *Wkvh, *Wkvl, *Woh, *Wol, *Cxh, *Cxl;
    cudaGetSymbolAddress((void**)&xh,   g_xh);
    cudaGetSymbolAddress((void**)&xl,   g_xl);
    cudaGetSymbolAddress((void**)&Wqh,  g_Wqh);
    cudaGetSymbolAddress((void**)&Wql,  g_Wql);
    cudaGetSymbolAddress((void**)&Wkvh, g_Wkvh);
    cudaGetSymbolAddress((void**)&Wkvl, g_Wkvl);
    cudaGetSymbolAddress((void**)&Woh,  g_Woh);
    cudaGetSymbolAddress((void**)&Wol,  g_Wol);
    cudaGetSymbolAddress((void**)&Cxh,  g_Cxh);
    cudaGetSymbolAddress((void**)&Cxl,  g_Cxl);

    cudaFuncSetAttribute(gemm_tc, cudaFuncAttributeMaxDynamicSharedMemorySize, GEMM_SMEM);
    cudaFuncSetAttribute(attn_mma, cudaFuncAttributeMaxDynamicSharedMemorySize, ATT_SMEM);

    const int M = Mrows;          // 4096
    const int NKV = 2 * Gn * HD;  // 1024

    // split x, transpose+split weights (Wk and Wv packed into one [1024][2048])
    fsplit<<<(M * DIN / 4 + 255) / 256, 256>>>(x, xh, xl, M * DIN);
    tsplit<<<dim3((2 * DOUT) / 32, DIN / 32), dim3(32, 8)>>>(Wq, Wqh, Wql, DIN, 2 * DOUT);
    tsplit<<<dim3((Gn * HD) / 32, DIN / 32), dim3(32, 8)>>>(Wk, Wkvh, Wkvl, DIN, Gn * HD);
    tsplit<<<dim3((Gn * HD) / 32, DIN / 32), dim3(32, 8)>>>(
        Wv, Wkvh + (size_t)(Gn * HD) * DIN, Wkvl + (size_t)(Gn * HD) * DIN, DIN, Gn * HD);
    tsplit<<<dim3(DIN / 32, DOUT / 32), dim3(32, 8)>>>(Wo, Woh, Wol, DOUT, DIN);

    // projections (HMMA split-bf16, cp.async, 3-stage)
    gemm_tc<<<dim3((2 * DOUT) / 128, M / 256), 256, GEMM_SMEM>>>(
        xh, xl, Wqh, Wql, QG, M, 2 * DOUT, DIN);
    gemm_tc<<<dim3(NKV / 128, M / 256), 256, GEMM_SMEM>>>(
        xh, xl, Wkvh, Wkvl, KV, M, NKV, DIN);

    // norm + rope -> bf16 hi/lo
    qnorm_rope<<<dim3(Sn, Hn, Bn), 128>>>(QG, qw, cosT, sinT, Qhp, Qlp);
    knorm_rope_vsplit<<<dim3(Sn, Gn, Bn), 128>>>(KV, kw, cosT, sinT,
                                                 Khp, Klp, Vhp, Vlp);

    // HMMA causal attention + gate (BQ=128), fused bf16 split epilogue
    attn_mma<<<dim3(Sn / 128, Hn, Bn), 256, ATT_SMEM>>>(
        Qhp, Qlp, Khp, Klp, Vhp, Vlp, QG, Cxh, Cxl);

    // output projection
    gemm_tc<<<dim3(DIN / 128, M / 256), 256, GEMM_SMEM>>>(
        Cxh, Cxl, Woh, Wol, out, M, DIN, DOUT);
}